// round 17
// baseline (speedup 1.0000x reference)
#include <cuda_runtime.h>
#include <cstdint>

#define T_DIM 1024
#define O_DIM 512
#define D_DIM 256
#define H_DIM 512
#define M_DIM (T_DIM + O_DIM)   // 1536

// Scratch (no allocations allowed)
__device__ float g_A[M_DIM * H_DIM];   // rows 0..1023: ht ; 1024..1535: ho + b1
__device__ float g_u[M_DIM];           // g_A[m] . W2

typedef unsigned long long u64;

__device__ __forceinline__ u64 addx2(u64 a, u64 b) {
    u64 r; asm("add.rn.f32x2 %0,%1,%2;" : "=l"(r) : "l"(a), "l"(b)); return r;
}
__device__ __forceinline__ u64 fmax2(u64 a, u64 b, u64 c) {
    u64 r; asm("fma.rn.f32x2 %0,%1,%2,%3;" : "=l"(r) : "l"(a), "l"(b), "l"(c)); return r;
}

union F2U { float2 f; u64 u; };

__device__ __forceinline__ u64 pack2(float x, float y) {
    F2U t; t.f = make_float2(x, y); return t.u;
}

__device__ __forceinline__ float to_tf32(float x) {
    uint32_t r; asm("cvt.rna.tf32.f32 %0, %1;" : "=r"(r) : "f"(x));
    return __uint_as_float(r);
}

__device__ __forceinline__ void cvt4(float4& v) {
    v.x = to_tf32(v.x); v.y = to_tf32(v.y);
    v.z = to_tf32(v.z); v.w = to_tf32(v.w);
}

__device__ __forceinline__ void mma_tf32(float* d,
                                         const uint32_t* a, const uint32_t* b,
                                         const float* c) {
    asm volatile(
        "mma.sync.aligned.m16n8k8.row.col.f32.tf32.tf32.f32 "
        "{%0,%1,%2,%3}, {%4,%5,%6,%7}, {%8,%9}, {%10,%11,%12,%13};"
        : "=f"(d[0]), "=f"(d[1]), "=f"(d[2]), "=f"(d[3])
        : "r"(a[0]), "r"(a[1]), "r"(a[2]), "r"(a[3]),
          "r"(b[0]), "r"(b[1]),
          "f"(c[0]), "f"(c[1]), "f"(c[2]), "f"(c[3]));
}

// ---------------------------------------------------------------------------
// Kernel 1: combined GEMM via tf32 mma.sync, double-buffered.
//   m < 1024:  g_A[m][h] = sum_k z_t[m][k]   * W1[k][h]
//   m >= 1024: g_A[m][h] = sum_k z_o[m-T][k] * W1[256+k][h] + b1[h]
// BM=64, BN=64, BK=32. 256 threads = 8 warps (2m x 4n), warp tile 32x16
// = 2x2 m16n8k8. grid = 8 x 24 = 192 CTAs. Double-buffered smem, one
// sync per 32-k chunk; next-chunk LDGs issued before the MMA block.
// Bank layout: Zs[m][36] -> fragment banks 4q+r (distinct), staging
// STS.128 distinct; Ws[k][72] -> fragment banks 8r+q (distinct).
// ---------------------------------------------------------------------------
__global__ __launch_bounds__(256) void gemm_kernel(
    const float* __restrict__ z_t, const float* __restrict__ z_o,
    const float* __restrict__ W1,  const float* __restrict__ b1)
{
    __shared__ __align__(16) float Zs[2][64][36];   // [buf][m][k]
    __shared__ __align__(16) float Ws[2][32][72];   // [buf][k][n]

    const int tid  = threadIdx.x;
    const int warp = tid >> 5;
    const int lane = tid & 31;
    const int q = lane >> 2;          // 0..7
    const int r = lane & 3;           // 0..3
    const int mo = (warp >> 2) * 32;  // warp m offset (0,32)
    const int no = (warp & 3) * 16;   // warp n offset (0,16,32,48)

    const int m0 = blockIdx.y * 64;
    const int h0 = blockIdx.x * 64;
    const bool is_o = (m0 >= T_DIM);
    const float* Z = is_o ? z_o : z_t;
    const int mrow0 = is_o ? (m0 - T_DIM) : m0;
    const int kbase = is_o ? D_DIM : 0;

    // staging mapping: A 64x32 (8 floats/thread), B 32x64 (8 floats/thread)
    const int zm = tid >> 2;          // 0..63
    const int zk = (tid & 3) * 8;     // 0,8,16,24
    const int wk = tid >> 3;          // 0..31
    const int wn = (tid & 7) * 8;     // 0..56

    const float* zp = Z + (mrow0 + zm) * D_DIM + zk;
    const float* wp = W1 + (kbase + wk) * H_DIM + h0 + wn;

    float acc[2][2][4] = {};

    // stage chunk 0
    {
        float4 a0 = *(const float4*)zp;
        float4 a1 = *(const float4*)(zp + 4);
        float4 c0 = *(const float4*)wp;
        float4 c1 = *(const float4*)(wp + 4);
        cvt4(a0); cvt4(a1); cvt4(c0); cvt4(c1);
        *(float4*)&Zs[0][zm][zk]     = a0;
        *(float4*)&Zs[0][zm][zk + 4] = a1;
        *(float4*)&Ws[0][wk][wn]     = c0;
        *(float4*)&Ws[0][wk][wn + 4] = c1;
    }
    __syncthreads();

    for (int c = 0; c < 8; ++c) {
        float4 na0, na1, nb0, nb1;
        if (c < 7) {
            const int ko = (c + 1) * 32;
            na0 = *(const float4*)(zp + ko);
            na1 = *(const float4*)(zp + ko + 4);
            nb0 = *(const float4*)(wp + ko * H_DIM);
            nb1 = *(const float4*)(wp + ko * H_DIM + 4);
        }
        const float (*Zb)[36] = Zs[c & 1];
        const float (*Wb)[72] = Ws[c & 1];
        #pragma unroll
        for (int s = 0; s < 4; ++s) {
            const int k0 = s * 8;
            uint32_t a[2][4], b[2][2];
            #pragma unroll
            for (int i = 0; i < 2; ++i) {
                a[i][0] = __float_as_uint(Zb[mo + 16 * i + q    ][k0 + r]);
                a[i][1] = __float_as_uint(Zb[mo + 16 * i + q + 8][k0 + r]);
                a[i][2] = __float_as_uint(Zb[mo + 16 * i + q    ][k0 + r + 4]);
                a[i][3] = __float_as_uint(Zb[mo + 16 * i + q + 8][k0 + r + 4]);
            }
            #pragma unroll
            for (int j = 0; j < 2; ++j) {
                b[j][0] = __float_as_uint(Wb[k0 + r    ][no + 8 * j + q]);
                b[j][1] = __float_as_uint(Wb[k0 + r + 4][no + 8 * j + q]);
            }
            #pragma unroll
            for (int i = 0; i < 2; ++i)
                #pragma unroll
                for (int j = 0; j < 2; ++j)
                    mma_tf32(acc[i][j], a[i], b[j], acc[i][j]);
        }
        if (c < 7) {
            cvt4(na0); cvt4(na1); cvt4(nb0); cvt4(nb1);
            const int nb = (c + 1) & 1;
            *(float4*)&Zs[nb][zm][zk]     = na0;
            *(float4*)&Zs[nb][zm][zk + 4] = na1;
            *(float4*)&Ws[nb][wk][wn]     = nb0;
            *(float4*)&Ws[nb][wk][wn + 4] = nb1;
        }
        __syncthreads();
    }

    // epilogue: c0:(q, r*2) c1:(q, r*2+1) c2:(q+8, r*2) c3:(q+8, r*2+1)
    #pragma unroll
    for (int i = 0; i < 2; ++i) {
        #pragma unroll
        for (int j = 0; j < 2; ++j) {
            const int ncol = h0 + no + 8 * j + r * 2;
            float bx = 0.f, by = 0.f;
            if (is_o) { bx = b1[ncol]; by = b1[ncol + 1]; }
            const int mr0 = m0 + mo + 16 * i + q;
            *(float2*)&g_A[mr0 * H_DIM + ncol] =
                make_float2(acc[i][j][0] + bx, acc[i][j][1] + by);
            *(float2*)&g_A[(mr0 + 8) * H_DIM + ncol] =
                make_float2(acc[i][j][2] + bx, acc[i][j][3] + by);
        }
    }
}

// ---------------------------------------------------------------------------
// Kernel 2: g_u[m] = g_A[m] . W2   (one warp per row)
// ---------------------------------------------------------------------------
__global__ __launch_bounds__(256) void rowdot_kernel(const float* __restrict__ W2)
{
    const int warp = blockIdx.x * 8 + (threadIdx.x >> 5);
    const int lane = threadIdx.x & 31;
    const float* row = g_A + warp * H_DIM;
    float s = 0.f;
    #pragma unroll
    for (int q = 0; q < 4; ++q) {
        const int idx = q * 128 + lane * 4;
        float4 a = *(const float4*)(row + idx);
        float4 w = *(const float4*)(W2 + idx);
        s += a.x * w.x + a.y * w.y + a.z * w.z + a.w * w.w;
    }
    #pragma unroll
    for (int d = 16; d >= 1; d >>= 1) s += __shfl_xor_sync(0xFFFFFFFFu, s, d);
    if (lane == 0) g_u[warp] = s;
}

// ---------------------------------------------------------------------------
// Kernel 3: main abs-bilinear loop (proven fastest config).
// out[t][o] = 0.505*(u[t]+u[T+o]) + 0.495 * sum_h |A[t][h]+A[T+o][h]| * w[h] + b2
// Tile 32(t) x 64(o), 128 threads, 4x4 per thread (o strided tx+16r),
// f32x2 packed, 16 chunks of 16 h-pairs. grid = 8 x 32 = 256 CTAs.
// ---------------------------------------------------------------------------
__global__ __launch_bounds__(128) void cfm_main_kernel(
    const float* __restrict__ W2, const float* __restrict__ b2,
    float* __restrict__ out)
{
    __shared__ __align__(16) u64 As[32][17];   // [t-row][h-pair]
    __shared__ __align__(16) u64 Bs[64][17];   // [o-row][h-pair]
    __shared__ u64 wsm[16];

    const int tid = threadIdx.x;
    const int tx = tid & 15;         // o: cols tx + 16r
    const int ty = tid >> 4;         // t: rows ty*4 + i  (0..7 -> 32 rows)
    const int t0 = blockIdx.y * 32;
    const int o0 = blockIdx.x * 64;

    const int arow = tid >> 2;           // 0..31
    const int apg  = (tid & 3) * 4;      // u64 cols 0,4,8,12 (8 floats)
    const int brow = tid >> 1;           // 0..63
    const int bpg  = (tid & 1) * 8;      // u64 cols 0,8      (16 floats)
    const float* Ap = g_A + (t0 + arow) * H_DIM + apg * 2;
    const float* Bp = g_A + (T_DIM + o0 + brow) * H_DIM + bpg * 2;

    u64 acc[4][4] = {};

    float4 ra[2], rb[4];
    ra[0] = *(const float4*)(Ap + 0);
    ra[1] = *(const float4*)(Ap + 4);
    #pragma unroll
    for (int r = 0; r < 4; ++r) rb[r] = *(const float4*)(Bp + r * 4);
    float2 wf = make_float2(0.f, 0.f);
    if (tid < 16) wf = *(const float2*)(W2 + tid * 2);

    const u64 ABSM = 0x7FFFFFFF7FFFFFFFULL;

    for (int c = 0; c < 16; ++c) {
        As[arow][apg + 0] = pack2(ra[0].x, ra[0].y);
        As[arow][apg + 1] = pack2(ra[0].z, ra[0].w);
        As[arow][apg + 2] = pack2(ra[1].x, ra[1].y);
        As[arow][apg + 3] = pack2(ra[1].z, ra[1].w);
        #pragma unroll
        for (int r = 0; r < 4; ++r) {
            Bs[brow][bpg + r * 2 + 0] = pack2(rb[r].x, rb[r].y);
            Bs[brow][bpg + r * 2 + 1] = pack2(rb[r].z, rb[r].w);
        }
        if (tid < 16) wsm[tid] = pack2(wf.x, wf.y);
        __syncthreads();
        if (c < 15) {
            const int off = (c + 1) * 32;   // 32 floats = 16 pairs per chunk
            ra[0] = *(const float4*)(Ap + off + 0);
            ra[1] = *(const float4*)(Ap + off + 4);
            #pragma unroll
            for (int r = 0; r < 4; ++r) rb[r] = *(const float4*)(Bp + off + r * 4);
            if (tid < 16) wf = *(const float2*)(W2 + (c + 1) * 32 + tid * 2);
        }
        #pragma unroll 8
        for (int k = 0; k < 16; ++k) {
            u64 a2[4], bv[4];
            #pragma unroll
            for (int i = 0; i < 4; ++i) a2[i] = As[ty * 4 + i][k];
            #pragma unroll
            for (int r = 0; r < 4; ++r) bv[r] = Bs[tx + 16 * r][k];
            const u64 w2 = wsm[k];
            #pragma unroll
            for (int i = 0; i < 4; ++i)
                #pragma unroll
                for (int j = 0; j < 4; ++j) {
                    u64 s = addx2(a2[i], bv[j]);
                    s &= ABSM;                       // |.| both lanes (2x LOP3, alu pipe)
                    acc[i][j] = fmax2(s, w2, acc[i][j]);
                }
        }
        __syncthreads();
    }

    const float b2v = b2[0];
    float ut[4], uo[4];
    #pragma unroll
    for (int i = 0; i < 4; ++i) ut[i] = g_u[t0 + ty * 4 + i];
    #pragma unroll
    for (int r = 0; r < 4; ++r) uo[r] = g_u[T_DIM + o0 + tx + 16 * r];

    #pragma unroll
    for (int i = 0; i < 4; ++i) {
        float* orow = out + (t0 + ty * 4 + i) * O_DIM + o0;
        #pragma unroll
        for (int r = 0; r < 4; ++r) {
            F2U cu; cu.u = acc[i][r];
            const float S = cu.f.x + cu.f.y;
            orow[tx + 16 * r] = 0.505f * (ut[i] + uo[r]) + 0.495f * S + b2v;
        }
    }
}

// ---------------------------------------------------------------------------
extern "C" void kernel_launch(void* const* d_in, const int* in_sizes, int n_in,
                              void* d_out, int out_size)
{
    const float* z_t = (const float*)d_in[0];   // [1024,256]
    const float* z_o = (const float*)d_in[1];   // [512,256]
    const float* W1  = (const float*)d_in[2];   // [512,512]
    const float* b1  = (const float*)d_in[3];   // [512]
    const float* W2  = (const float*)d_in[4];   // [512,1]
    const float* b2  = (const float*)d_in[5];   // [1]
    float* out = (float*)d_out;                 // [1024,512]

    (void)in_sizes; (void)n_in; (void)out_size;

    gemm_kernel<<<dim3(H_DIM / 64, M_DIM / 64), 256>>>(z_t, z_o, W1, b1);
    rowdot_kernel<<<M_DIM / 8, 256>>>(W2);
    cfm_main_kernel<<<dim3(O_DIM / 64, T_DIM / 32), 128>>>(W2, b2, out);
}